// round 1
// baseline (speedup 1.0000x reference)
#include <cuda_runtime.h>

// HarmonicAwaredAttention — fully fused: one block per sequence n = b*T + t.
// F=128 tokens, C=128 channels, H=2 heads, DH=64, L=4 layers.
// Harmonic mask => sparse attention over offsets {0,±48,±76,±96,±111,±124}.

#define FDIM 128
#define CDIM 128
#define TT   512
#define NL   4
#define LDA  132          // padded smem row stride (floats)
#define NTHREADS 256

__device__ __forceinline__ unsigned long long pack2(float a) {
    unsigned long long r;
    asm("mov.b64 %0, {%1, %1};" : "=l"(r) : "r"(__float_as_uint(a)));
    return r;
}
__device__ __forceinline__ void ffma2(unsigned long long& d, unsigned long long a,
                                      unsigned long long b) {
    asm("fma.rn.f32x2 %0, %1, %2, %0;" : "+l"(d) : "l"(a), "l"(b));
}

// C[128,128] = A[128,128](smem) @ W[128,128](gmem,L2) + bias.  In-place (Co==A) safe:
// all A reads complete before the final sync; writes happen after it.
__device__ void gemm128(const float* __restrict__ A, const float* __restrict__ gW,
                        const float* __restrict__ gB, float* __restrict__ Co,
                        float* __restrict__ wtile, int tid)
{
    const int tx = tid & 15, ty = tid >> 4;
    const int r0 = ty * 8, c0 = tx * 4;

    unsigned long long acc[8][4];
#pragma unroll
    for (int i = 0; i < 8; i++)
#pragma unroll
        for (int p = 0; p < 4; p++) acc[i][p] = 0ull;

    const int wrow = tid >> 4;         // 0..15
    const int wcol = (tid & 15) * 8;   // 0..120

    // prefetch first weight slab into registers
    float4 w0 = *(const float4*)&gW[wrow * 128 + wcol];
    float4 w1 = *(const float4*)&gW[wrow * 128 + wcol + 4];

    for (int k0 = 0; k0 < 128; k0 += 16) {
        __syncthreads();                       // previous slab fully consumed
        *(float4*)&wtile[wrow * 128 + wcol]     = w0;
        *(float4*)&wtile[wrow * 128 + wcol + 4] = w1;
        if (k0 + 16 < 128) {                   // prefetch next slab (hidden by compute)
            w0 = *(const float4*)&gW[(k0 + 16 + wrow) * 128 + wcol];
            w1 = *(const float4*)&gW[(k0 + 16 + wrow) * 128 + wcol + 4];
        }
        __syncthreads();                       // slab visible

#pragma unroll
        for (int kk = 0; kk < 16; kk += 4) {
            float4 a4[8];
#pragma unroll
            for (int i = 0; i < 8; i++)
                a4[i] = *(const float4*)&A[(r0 + i) * LDA + k0 + kk];
#pragma unroll
            for (int s = 0; s < 4; s++) {
                const float* wr = &wtile[(kk + s) * 128];
                ulonglong2 bA = *(const ulonglong2*)&wr[c0];
                ulonglong2 bB = *(const ulonglong2*)&wr[c0 + 64];
#pragma unroll
                for (int i = 0; i < 8; i++) {
                    float av = ((const float*)&a4[i])[s];
                    unsigned long long a2 = pack2(av);
                    ffma2(acc[i][0], a2, bA.x);
                    ffma2(acc[i][1], a2, bA.y);
                    ffma2(acc[i][2], a2, bB.x);
                    ffma2(acc[i][3], a2, bB.y);
                }
            }
        }
    }
    __syncthreads();   // all A reads done before any Co writes (enables in-place)

    const float b0 = gB[c0],      b1 = gB[c0 + 1],  b2 = gB[c0 + 2],  b3 = gB[c0 + 3];
    const float b4 = gB[c0 + 64], b5 = gB[c0 + 65], b6 = gB[c0 + 66], b7 = gB[c0 + 67];
#pragma unroll
    for (int i = 0; i < 8; i++) {
        float* crow = &Co[(r0 + i) * LDA];
        float2 v;
        v.x = __uint_as_float((unsigned)acc[i][0])         + b0;
        v.y = __uint_as_float((unsigned)(acc[i][0] >> 32)) + b1;
        *(float2*)&crow[c0] = v;
        v.x = __uint_as_float((unsigned)acc[i][1])         + b2;
        v.y = __uint_as_float((unsigned)(acc[i][1] >> 32)) + b3;
        *(float2*)&crow[c0 + 2] = v;
        v.x = __uint_as_float((unsigned)acc[i][2])         + b4;
        v.y = __uint_as_float((unsigned)(acc[i][2] >> 32)) + b5;
        *(float2*)&crow[c0 + 64] = v;
        v.x = __uint_as_float((unsigned)acc[i][3])         + b6;
        v.y = __uint_as_float((unsigned)(acc[i][3] >> 32)) + b7;
        *(float2*)&crow[c0 + 66] = v;
    }
    __syncthreads();   // writeback visible to all
}

// Sparse harmonic attention. Thread (row = tid>>1, head = tid&1) owns one query row.
// Reads q from pQ, K/V from smem; overwrites its OWN pQ region with o (disjoint
// regions per thread -> no internal sync needed).
__device__ void attention(float* __restrict__ pQ, const float* __restrict__ pK,
                          const float* __restrict__ pV, int tid)
{
    const int row  = tid >> 1;
    const int hoff = (tid & 1) * 64;
    const int deltas[11] = {-124, -111, -96, -76, -48, 0, 48, 76, 96, 111, 124};

    float4 q4[16];
    const float* qp = &pQ[row * LDA + hoff];
#pragma unroll
    for (int i = 0; i < 16; i++) q4[i] = *(const float4*)&qp[i * 4];

    float sv[11];
#pragma unroll
    for (int d = 0; d < 11; d++) {
        int j = row + deltas[d];
        float s = -1e30f;
        if ((unsigned)j < 128u) {
            const float* kp = &pK[j * LDA + hoff];
            float a = 0.f;
#pragma unroll
            for (int i = 0; i < 16; i++) {
                float4 kv = *(const float4*)&kp[i * 4];
                a = fmaf(q4[i].x, kv.x, a);
                a = fmaf(q4[i].y, kv.y, a);
                a = fmaf(q4[i].z, kv.z, a);
                a = fmaf(q4[i].w, kv.w, a);
            }
            s = a * 0.125f;    // 1/sqrt(64)
        }
        sv[d] = s;
    }
    float m = sv[0];
#pragma unroll
    for (int d = 1; d < 11; d++) m = fmaxf(m, sv[d]);
    float ev[11];
    float sum = 0.f;
#pragma unroll
    for (int d = 0; d < 11; d++) { float e = expf(sv[d] - m); ev[d] = e; sum += e; }
    const float inv = 1.f / sum;

    float4 o4[16];
#pragma unroll
    for (int i = 0; i < 16; i++) o4[i] = make_float4(0.f, 0.f, 0.f, 0.f);
#pragma unroll
    for (int d = 0; d < 11; d++) {
        int j = row + deltas[d];
        if ((unsigned)j < 128u) {
            float w = ev[d] * inv;
            const float* vp = &pV[j * LDA + hoff];
#pragma unroll
            for (int i = 0; i < 16; i++) {
                float4 vv = *(const float4*)&vp[i * 4];
                o4[i].x = fmaf(w, vv.x, o4[i].x);
                o4[i].y = fmaf(w, vv.y, o4[i].y);
                o4[i].z = fmaf(w, vv.z, o4[i].z);
                o4[i].w = fmaf(w, vv.w, o4[i].w);
            }
        }
    }
    float* op = &pQ[row * LDA + hoff];
#pragma unroll
    for (int i = 0; i < 16; i++) *(float4*)&op[i * 4] = o4[i];
}

extern __shared__ float smem[];

__global__ void __launch_bounds__(NTHREADS, 1)
hattn_kernel(const float* __restrict__ x,
             const float* __restrict__ Wq, const float* __restrict__ bq,
             const float* __restrict__ Wk, const float* __restrict__ bk,
             const float* __restrict__ Wv, const float* __restrict__ bv,
             const float* __restrict__ Wo, const float* __restrict__ bo,
             float* __restrict__ out)
{
    float* bufA  = smem;
    float* bufB  = bufA + 128 * LDA;
    float* bufC  = bufB + 128 * LDA;
    float* wtile = bufC + 128 * LDA;   // [16][128]

    const int tid = threadIdx.x;
    const int b   = blockIdx.x / TT;
    const int t   = blockIdx.x % TT;
    const float* xb = x + (size_t)b * CDIM * TT * FDIM + (size_t)t * FDIM;

    float* pH = bufA;
    float* pK = bufB;
    float* pV = bufC;

    // h[f][c] = x[b][c][t][f] + pe[f][c]
    for (int idx = tid; idx < CDIM * FDIM; idx += NTHREADS) {
        int c = idx >> 7, f = idx & 127;
        float e     = (float)(c & ~1) * (1.0f / 128.0f);
        float denom = exp2f(e * 13.287712379549449f);   // 10000^(i/128)
        float ang   = (float)f / denom;
        float pe    = (c & 1) ? cosf(ang) : sinf(ang);
        pH[f * LDA + c] = xb[(size_t)c * TT * FDIM + f] + pe;
    }
    // gemm's loop-top sync orders the smem fill before first reads

    for (int l = 0; l < NL; l++) {
        const float* wq = Wq + l * 16384; const float* bqv = bq + l * 128;
        const float* wk = Wk + l * 16384; const float* bkv = bk + l * 128;
        const float* wv = Wv + l * 16384; const float* bvv = bv + l * 128;
        const float* wo = Wo + l * 16384; const float* bov = bo + l * 128;

        gemm128(pH, wk, bkv, pK, wtile, tid);   // K
        gemm128(pH, wv, bvv, pV, wtile, tid);   // V
        gemm128(pH, wq, bqv, pH, wtile, tid);   // Q (in-place over H)
        attention(pH, pK, pV, tid);             // O overwrites Q (per-thread disjoint)
        __syncthreads();
        gemm128(pH, wo, bov, pV, wtile, tid);   // H_new = O @ Wo  -> pV
        float* tmp = pH; pH = pV; pV = tmp;
    }

    // out[b][c][t][f] = h[f][c]
    float* ob = out + (size_t)b * CDIM * TT * FDIM + (size_t)t * FDIM;
    for (int idx = tid; idx < CDIM * FDIM; idx += NTHREADS) {
        int c = idx >> 7, f = idx & 127;
        ob[(size_t)c * TT * FDIM + f] = pH[f * LDA + c];
    }
}

extern "C" void kernel_launch(void* const* d_in, const int* in_sizes, int n_in,
                              void* d_out, int out_size)
{
    const float* x  = (const float*)d_in[0];
    const float* Wq = (const float*)d_in[1];
    const float* bq = (const float*)d_in[2];
    const float* Wk = (const float*)d_in[3];
    const float* bk = (const float*)d_in[4];
    const float* Wv = (const float*)d_in[5];
    const float* bv = (const float*)d_in[6];
    const float* Wo = (const float*)d_in[7];
    const float* bo = (const float*)d_in[8];
    float* out = (float*)d_out;

    const int NB = in_sizes[0] / (CDIM * TT * FDIM);   // batch (4)
    const size_t smem_bytes = (size_t)(3 * 128 * LDA + 16 * 128) * sizeof(float); // 210944

    cudaFuncSetAttribute(hattn_kernel, cudaFuncAttributeMaxDynamicSharedMemorySize,
                         (int)smem_bytes);
    hattn_kernel<<<NB * TT, NTHREADS, smem_bytes>>>(x, Wq, bq, Wk, bk, Wv, bv, Wo, bo, out);
}